// round 5
// baseline (speedup 1.0000x reference)
#include <cuda_runtime.h>
#include <cstdint>

#define ROUNDS 64
#define HID 256
#define BATCH 65536
#define TILE_M 128
#define NTILES (BATCH / TILE_M)      // 512
#define MAT_BYTES (HID * HID)        // 65536 s8 per round matrix

// Pre-converted, pre-swizzled s8 matrices (SMEM image layout), 4 MB. Lives in L2.
__device__ __align__(128) unsigned char g_mat[ROUNDS * MAT_BYTES];

// ---------------- SMEM layout (fits 2 CTAs/SM) ----------------
#define OF_NOISE 0
#define OF_A     1024
#define OF_B     (1024 + 32768)
#define SMEM_TOTAL (OF_B + 65536)    // 99328 bytes

// ---------------- helpers ----------------
__device__ __forceinline__ uint32_t smem_u32(const void* p) {
    uint32_t a;
    asm("{ .reg .u64 t; cvta.to.shared.u64 t, %1; cvt.u32.u64 %0, t; }" : "=r"(a) : "l"(p));
    return a;
}

// byte address inside a [rows x 256B] tile with 16B-chunk XOR swizzle
__device__ __forceinline__ uint32_t swz(uint32_t row, uint32_t col) {
    return row * 256u + ((((col >> 4) ^ (row & 7u)) << 4) | (col & 15u));
}

__device__ __forceinline__ void ldm_x4(uint32_t addr, uint32_t& r0, uint32_t& r1,
                                       uint32_t& r2, uint32_t& r3) {
    asm volatile("ldmatrix.sync.aligned.m8n8.x4.shared.b16 {%0,%1,%2,%3}, [%4];"
                 : "=r"(r0), "=r"(r1), "=r"(r2), "=r"(r3) : "r"(addr));
}

__device__ __forceinline__ void mma_s8(int* c, uint32_t a0, uint32_t a1, uint32_t a2,
                                       uint32_t a3, uint32_t b0, uint32_t b1) {
    asm volatile(
        "mma.sync.aligned.m16n8k32.row.col.s32.s8.s8.s32 "
        "{%0,%1,%2,%3}, {%4,%5,%6,%7}, {%8,%9}, {%0,%1,%2,%3};"
        : "+r"(c[0]), "+r"(c[1]), "+r"(c[2]), "+r"(c[3])
        : "r"(a0), "r"(a1), "r"(a2), "r"(a3), "r"(b0), "r"(b1));
}

__device__ __forceinline__ void issue_b(uint32_t dst, int r, int tid) {
    const unsigned char* src = g_mat + (size_t)r * MAT_BYTES;
#pragma unroll
    for (int j = 0; j < 16; j++) {
        uint32_t off = (uint32_t)(tid + (j << 8)) << 4;
        asm volatile("cp.async.cg.shared.global [%0], [%1], 16;"
                     :: "r"(dst + off), "l"(src + off) : "memory");
    }
}

// exact C fmod(v,2) for ints: {-1,0,1} with sign of v
__device__ __forceinline__ int mod2i(int v) {
    return (v & 1) * ((v >> 31) | 1);
}

// ---------------- Kernel 1: f32 matrices -> s8 pre-swizzled image ----------------
__global__ void cvt_mats_kernel(const float* __restrict__ m) {
    uint32_t i = blockIdx.x * 256u + threadIdx.x;       // group of 4 elements
    const float4 v = *(const float4*)(m + (size_t)i * 4);
    uint32_t e0 = v.x > 0.5f ? 0x01u : (v.x < -0.5f ? 0xFFu : 0x00u);
    uint32_t e1 = v.y > 0.5f ? 0x01u : (v.y < -0.5f ? 0xFFu : 0x00u);
    uint32_t e2 = v.z > 0.5f ? 0x01u : (v.z < -0.5f ? 0xFFu : 0x00u);
    uint32_t e3 = v.w > 0.5f ? 0x01u : (v.w < -0.5f ? 0xFFu : 0x00u);
    uint32_t pk = e0 | (e1 << 8) | (e2 << 16) | (e3 << 24);
    uint32_t idx = i << 2;
    uint32_t r = idx >> 16, n = (idx >> 8) & 255u, k = idx & 255u;
    *(uint32_t*)(g_mat + (r << 16) + swz(n, k)) = pk;   // k%16 is 4-aligned here
}

// ---------------- Kernel 2: 64 sequential rounds per 128-row tile ----------------
// Warp tiling: warp w -> m-group mg = w&3 (rows mg*32..+32), n-half nh = w>>2
// (cols nh*128..+128). A rows are private to warp pair {mg, mg+4}:
// the A write-after-read hazard is covered by a pairwise named barrier.
__global__ __launch_bounds__(256, 2)
void tenshash_kernel(const float* __restrict__ state,
                     const float* __restrict__ noise,
                     float* __restrict__ out) {
    extern __shared__ unsigned char smem[];
    uint32_t sb = smem_u32(smem);
    int tid = threadIdx.x, w = tid >> 5, l = tid & 31;
    int* nsm = (int*)(smem + OF_NOISE);
    const int gbase = blockIdx.x * TILE_M;
    const int mg = w & 3, nh = w >> 2;

    // stage noise[0]
    nsm[tid] = (int)noise[tid];

    // init A from state (float {0,1} -> s8), swizzled, u16-packed
    for (int i = tid; i < TILE_M * HID / 2; i += 256) {
        int row = i >> 7;
        int k = (i & 127) << 1;
        const float2 v = *(const float2*)(state + (size_t)(gbase + row) * HID + k);
        uint32_t b0 = v.x > 0.5f ? 1u : 0u;
        uint32_t b1 = v.y > 0.5f ? 1u : 0u;
        *(unsigned short*)(smem + OF_A + swz((uint32_t)row, (uint32_t)k)) =
            (unsigned short)(b0 | (b1 << 8));
    }

    // prologue: prefetch B for round 0
    issue_b(sb + OF_B, 0, tid);
    asm volatile("cp.async.commit_group;" ::: "memory");

    // lane-invariant addressing pieces
    const uint32_t rowA0 = (uint32_t)(mg * 32) + (l & 15);        // A tile t=0
    const uint32_t rowA1 = rowA0 + 16;                            // A tile t=1
    const uint32_t sA0 = rowA0 & 7u, sA1 = rowA1 & 7u;
    const uint32_t aHalf = (uint32_t)(l >> 4);                    // k-chunk half
    const uint32_t bHalf = ((uint32_t)l >> 3) & 1u;
    const int erow0 = mg * 32 + (l >> 2);                         // epilogue rows
    const int ecol = nh * 128 + ((l & 3) << 1);
    const uint32_t Acur = sb + OF_A;
    const uint32_t Bcur = sb + OF_B;

#pragma unroll 1
    for (int r = 0; r < ROUNDS; r++) {
        asm volatile("cp.async.wait_group 0;" ::: "memory");
        __syncthreads();    // B[r] ready; A stores + noise from r-1 visible
        const bool last = (r == ROUNDS - 1);
        uint32_t pk32[32];  // staged next-A: [ch*16 + t*8 + j]

#pragma unroll 1
        for (int ch = 0; ch < 2; ch++) {           // two 64-col n-chunks
            int acc[2][8][4];
#pragma unroll
            for (int t = 0; t < 2; t++)
#pragma unroll
                for (int j = 0; j < 8; j++)
                    acc[t][j][0] = acc[t][j][1] = acc[t][j][2] = acc[t][j][3] = 0;

#pragma unroll
            for (int kk = 0; kk < 8; kk++) {       // K = 8 x k32
                uint32_t a0[4], a1[4];
                ldm_x4(Acur + rowA0 * 256u + ((((uint32_t)(2 * kk) + aHalf) ^ sA0) << 4),
                       a0[0], a0[1], a0[2], a0[3]);
                ldm_x4(Acur + rowA1 * 256u + ((((uint32_t)(2 * kk) + aHalf) ^ sA1) << 4),
                       a1[0], a1[1], a1[2], a1[3]);
#pragma unroll
                for (int p = 0; p < 4; p++) {      // 16 cols (2 n-tiles) per x4
                    uint32_t bb[4];
                    uint32_t n = (uint32_t)(nh * 128 + ch * 64 + p * 16) +
                                 (((uint32_t)l >> 4) << 3) + (l & 7);
                    uint32_t cb = (uint32_t)(2 * kk) + bHalf;
                    ldm_x4(Bcur + n * 256u + ((cb ^ (n & 7u)) << 4),
                           bb[0], bb[1], bb[2], bb[3]);
                    mma_s8(acc[0][2 * p + 0], a0[0], a0[1], a0[2], a0[3], bb[0], bb[1]);
                    mma_s8(acc[0][2 * p + 1], a0[0], a0[1], a0[2], a0[3], bb[2], bb[3]);
                    mma_s8(acc[1][2 * p + 0], a1[0], a1[1], a1[2], a1[3], bb[0], bb[1]);
                    mma_s8(acc[1][2 * p + 1], a1[0], a1[1], a1[2], a1[3], bb[2], bb[3]);
                }
            }

            // epilogue: v = (acc + noise) % 2, cheap sign-exact mod + PRMT pack
#pragma unroll
            for (int j = 0; j < 8; j++) {
                int col0 = ecol + (ch << 6) + (j << 3);
                int n0 = nsm[col0], n1 = nsm[col0 + 1];
#pragma unroll
                for (int t = 0; t < 2; t++) {
                    int m00 = mod2i(acc[t][j][0] + n0);
                    int m01 = mod2i(acc[t][j][1] + n1);
                    int m10 = mod2i(acc[t][j][2] + n0);
                    int m11 = mod2i(acc[t][j][3] + n1);
                    if (!last) {
                        uint32_t t0 = __byte_perm((uint32_t)m00, (uint32_t)m01, 0x0040);
                        uint32_t t1 = __byte_perm((uint32_t)m10, (uint32_t)m11, 0x0040);
                        pk32[ch * 16 + t * 8 + j] = __byte_perm(t0, t1, 0x5410);
                    } else {
                        int r0loc = erow0 + t * 16, r1loc = r0loc + 8;
                        float2 o0 = make_float2((float)m00, (float)m01);
                        float2 o1 = make_float2((float)m10, (float)m11);
                        *(float2*)(out + (size_t)(gbase + r0loc) * HID + col0) = o0;
                        *(float2*)(out + (size_t)(gbase + r1loc) * HID + col0) = o1;
                    }
                }
            }
        }

        if (last) break;

        // pairwise barrier: both warps of this mg are done READING A rows
        asm volatile("bar.sync %0, %1;" :: "r"(mg + 1), "r"(64) : "memory");

        // store staged next-A (overlaps other pairs' compute)
#pragma unroll
        for (int ch = 0; ch < 2; ch++)
#pragma unroll
            for (int t = 0; t < 2; t++)
#pragma unroll
                for (int j = 0; j < 8; j++) {
                    uint32_t v = pk32[ch * 16 + t * 8 + j];
                    int col0 = ecol + (ch << 6) + (j << 3);
                    int r0loc = erow0 + t * 16, r1loc = r0loc + 8;
                    *(unsigned short*)(smem + OF_A + swz((uint32_t)r0loc, (uint32_t)col0)) =
                        (unsigned short)(v & 0xFFFFu);
                    *(unsigned short*)(smem + OF_A + swz((uint32_t)r1loc, (uint32_t)col0)) =
                        (unsigned short)(v >> 16);
                }

        __syncthreads();    // all warps done reading B[r]; A stores visible

        // issue next B load (same single buffer) + stage next noise
        issue_b(Bcur, r + 1, tid);
        asm volatile("cp.async.commit_group;" ::: "memory");
        nsm[tid] = (int)noise[((r + 1) << 8) + tid];
    }
}

// ---------------- launch ----------------
extern "C" void kernel_launch(void* const* d_in, const int* in_sizes, int n_in,
                              void* d_out, int out_size) {
    const float* state = (const float*)d_in[0];
    const float* mats  = (const float*)d_in[1];
    const float* noise = (const float*)d_in[2];
    float* out = (float*)d_out;

    cvt_mats_kernel<<<ROUNDS * MAT_BYTES / 4 / 256, 256>>>(mats);

    cudaFuncSetAttribute(tenshash_kernel,
                         cudaFuncAttributeMaxDynamicSharedMemorySize, SMEM_TOTAL);
    tenshash_kernel<<<NTILES, 256, SMEM_TOTAL>>>(state, noise, out);
}

// round 6
// speedup vs baseline: 1.0460x; 1.0460x over previous
#include <cuda_runtime.h>
#include <cstdint>

#define ROUNDS 64
#define HID 256
#define BATCH 65536
#define TILE_M 128
#define NTILES (BATCH / TILE_M)      // 512
#define MAT_BYTES (HID * HID)        // 65536 s8 per round matrix

// Pre-converted, pre-swizzled s8 matrices (SMEM image layout), 4 MB. Lives in L2.
__device__ __align__(128) unsigned char g_mat[ROUNDS * MAT_BYTES];

// ---------------- SMEM layout (fits 2 CTAs/SM) ----------------
#define OF_NOISE 0                   // two 1KB noise buffers
#define OF_A     2048
#define OF_B     (2048 + 32768)
#define SMEM_TOTAL (OF_B + 65536)    // 100352 bytes

// ---------------- helpers ----------------
__device__ __forceinline__ uint32_t smem_u32(const void* p) {
    uint32_t a;
    asm("{ .reg .u64 t; cvta.to.shared.u64 t, %1; cvt.u32.u64 %0, t; }" : "=r"(a) : "l"(p));
    return a;
}

// byte address inside a [rows x 256B] tile with 16B-chunk XOR swizzle
__device__ __forceinline__ uint32_t swz(uint32_t row, uint32_t col) {
    return row * 256u + ((((col >> 4) ^ (row & 7u)) << 4) | (col & 15u));
}

__device__ __forceinline__ void ldm_x4(uint32_t addr, uint32_t& r0, uint32_t& r1,
                                       uint32_t& r2, uint32_t& r3) {
    asm volatile("ldmatrix.sync.aligned.m8n8.x4.shared.b16 {%0,%1,%2,%3}, [%4];"
                 : "=r"(r0), "=r"(r1), "=r"(r2), "=r"(r3) : "r"(addr));
}

__device__ __forceinline__ void mma_s8(int* c, uint32_t a0, uint32_t a1, uint32_t a2,
                                       uint32_t a3, uint32_t b0, uint32_t b1) {
    asm volatile(
        "mma.sync.aligned.m16n8k32.row.col.s32.s8.s8.s32 "
        "{%0,%1,%2,%3}, {%4,%5,%6,%7}, {%8,%9}, {%0,%1,%2,%3};"
        : "+r"(c[0]), "+r"(c[1]), "+r"(c[2]), "+r"(c[3])
        : "r"(a0), "r"(a1), "r"(a2), "r"(a3), "r"(b0), "r"(b1));
}

__device__ __forceinline__ void issue_b(uint32_t dst, int r, int tid) {
    const unsigned char* src = g_mat + (size_t)r * MAT_BYTES;
#pragma unroll
    for (int j = 0; j < 16; j++) {
        uint32_t off = (uint32_t)(tid + (j << 8)) << 4;
        asm volatile("cp.async.cg.shared.global [%0], [%1], 16;"
                     :: "r"(dst + off), "l"(src + off) : "memory");
    }
}

// ---------------- Kernel 1: f32 matrices -> s8 pre-swizzled image ----------------
__global__ void cvt_mats_kernel(const float* __restrict__ m) {
    uint32_t i = blockIdx.x * 256u + threadIdx.x;       // group of 4 elements
    const float4 v = *(const float4*)(m + (size_t)i * 4);
    uint32_t e0 = v.x > 0.5f ? 0x01u : (v.x < -0.5f ? 0xFFu : 0x00u);
    uint32_t e1 = v.y > 0.5f ? 0x01u : (v.y < -0.5f ? 0xFFu : 0x00u);
    uint32_t e2 = v.z > 0.5f ? 0x01u : (v.z < -0.5f ? 0xFFu : 0x00u);
    uint32_t e3 = v.w > 0.5f ? 0x01u : (v.w < -0.5f ? 0xFFu : 0x00u);
    uint32_t pk = e0 | (e1 << 8) | (e2 << 16) | (e3 << 24);
    uint32_t idx = i << 2;
    uint32_t r = idx >> 16, n = (idx >> 8) & 255u, k = idx & 255u;
    *(uint32_t*)(g_mat + (r << 16) + swz(n, k)) = pk;   // k%16 is 4-aligned here
}

// ---------------- Kernel 2: 64 sequential rounds per 128-row tile ----------------
// Warp tiling: warp w -> m-group mg = w&3 (rows mg*32..+32), n-half nh = w>>2
// (cols nh*128..+128). Single A/B smem buffers; double-buffered noise.
// Per round: [waitB+sync] ch0 kk + epi0 | ch1 kk | [sync, issue B(r+1)] |
// epi1 | A-store (shfl-paired u32) | noise stage.
__global__ __launch_bounds__(256, 2)
void tenshash_kernel(const float* __restrict__ state,
                     const float* __restrict__ noise,
                     float* __restrict__ out) {
    extern __shared__ unsigned char smem[];
    uint32_t sb = smem_u32(smem);
    int tid = threadIdx.x, w = tid >> 5, l = tid & 31;
    const int gbase = blockIdx.x * TILE_M;
    const int mg = w & 3, nh = w >> 2;

    // stage noise[0] into buffer 0
    ((int*)(smem + OF_NOISE))[tid] = (int)noise[tid];

    // init A from state (float {0,1} -> s8), swizzled, u16-packed
    for (int i = tid; i < TILE_M * HID / 2; i += 256) {
        int row = i >> 7;
        int k = (i & 127) << 1;
        const float2 v = *(const float2*)(state + (size_t)(gbase + row) * HID + k);
        uint32_t b0 = v.x > 0.5f ? 1u : 0u;
        uint32_t b1 = v.y > 0.5f ? 1u : 0u;
        *(unsigned short*)(smem + OF_A + swz((uint32_t)row, (uint32_t)k)) =
            (unsigned short)(b0 | (b1 << 8));
    }

    // prologue: prefetch B for round 0
    issue_b(sb + OF_B, 0, tid);
    asm volatile("cp.async.commit_group;" ::: "memory");

    // lane-invariant addressing pieces
    const uint32_t rowA0 = (uint32_t)(mg * 32) + (l & 15);        // A tile t=0
    const uint32_t rowA1 = rowA0 + 16;                            // A tile t=1
    const uint32_t sA0 = rowA0 & 7u, sA1 = rowA1 & 7u;
    const uint32_t aHalf = (uint32_t)(l >> 4);                    // k-chunk half
    const uint32_t bHalf = ((uint32_t)l >> 3) & 1u;
    const int erow0 = mg * 32 + (l >> 2);                         // epilogue rows
    const int ecol = nh * 128 + ((l & 3) << 1);
    const int colqbase = nh * 128 + (((l >> 1) & 1) << 2);        // u32-store col
    const uint32_t Acur = sb + OF_A;
    const uint32_t Bcur = sb + OF_B;

#define KK_LOOP(CH, ACC)                                                          \
    _Pragma("unroll")                                                             \
    for (int kk = 0; kk < 8; kk++) {                                              \
        uint32_t a0[4], a1[4];                                                    \
        ldm_x4(Acur + rowA0 * 256u + ((((uint32_t)(2 * kk) + aHalf) ^ sA0) << 4), \
               a0[0], a0[1], a0[2], a0[3]);                                       \
        ldm_x4(Acur + rowA1 * 256u + ((((uint32_t)(2 * kk) + aHalf) ^ sA1) << 4), \
               a1[0], a1[1], a1[2], a1[3]);                                       \
        _Pragma("unroll")                                                         \
        for (int p = 0; p < 4; p++) {                                             \
            uint32_t bb[4];                                                       \
            uint32_t n = (uint32_t)(nh * 128 + (CH) * 64 + p * 16) +              \
                         (((uint32_t)l >> 4) << 3) + (l & 7);                     \
            uint32_t cb = (uint32_t)(2 * kk) + bHalf;                             \
            ldm_x4(Bcur + n * 256u + ((cb ^ (n & 7u)) << 4),                      \
                   bb[0], bb[1], bb[2], bb[3]);                                   \
            mma_s8(ACC[0][2 * p + 0], a0[0], a0[1], a0[2], a0[3], bb[0], bb[1]);  \
            mma_s8(ACC[0][2 * p + 1], a0[0], a0[1], a0[2], a0[3], bb[2], bb[3]);  \
            mma_s8(ACC[1][2 * p + 0], a1[0], a1[1], a1[2], a1[3], bb[0], bb[1]);  \
            mma_s8(ACC[1][2 * p + 1], a1[0], a1[1], a1[2], a1[3], bb[2], bb[3]);  \
        }                                                                         \
    }

#define EPILOGUE(CH, ACC)                                                         \
    _Pragma("unroll")                                                             \
    for (int j = 0; j < 8; j++) {                                                 \
        int col0 = ecol + ((CH) << 6) + (j << 3);                                 \
        int n0 = nsmr[col0], n1 = nsmr[col0 + 1];                                 \
        _Pragma("unroll")                                                         \
        for (int t = 0; t < 2; t++) {                                             \
            int v00 = (ACC[t][j][0] + n0) % 2, v01 = (ACC[t][j][1] + n1) % 2;     \
            int v10 = (ACC[t][j][2] + n0) % 2, v11 = (ACC[t][j][3] + n1) % 2;     \
            if (!last) {                                                          \
                pk[(CH) * 16 + t * 8 + j] =                                       \
                    (v00 & 255) | ((v01 & 255) << 8) |                            \
                    ((v10 & 255) << 16) | ((uint32_t)(v11 & 255) << 24);          \
            } else {                                                              \
                int r0loc = erow0 + t * 16, r1loc = r0loc + 8;                    \
                float2 o0 = make_float2((float)v00, (float)v01);                  \
                float2 o1 = make_float2((float)v10, (float)v11);                  \
                *(float2*)(out + (size_t)(gbase + r0loc) * HID + col0) = o0;      \
                *(float2*)(out + (size_t)(gbase + r1loc) * HID + col0) = o1;      \
            }                                                                     \
        }                                                                         \
    }

#pragma unroll 1
    for (int r = 0; r < ROUNDS; r++) {
        asm volatile("cp.async.wait_group 0;" ::: "memory");
        __syncthreads();    // B[r] ready; A stores + noise from r-1 visible
        const bool last = (r == ROUNDS - 1);
        const int* nsmr = (const int*)(smem + OF_NOISE + ((r & 1) << 10));
        uint32_t pk[32];

        // ----- ch = 0: compute + epilogue (pre-barrier; reads noise buf r&1)
        {
            int acc[2][8][4];
#pragma unroll
            for (int t = 0; t < 2; t++)
#pragma unroll
                for (int j = 0; j < 8; j++)
                    acc[t][j][0] = acc[t][j][1] = acc[t][j][2] = acc[t][j][3] = 0;
            KK_LOOP(0, acc)
            EPILOGUE(0, acc)
        }

        // ----- ch = 1: compute only
        int acc1[2][8][4];
#pragma unroll
        for (int t = 0; t < 2; t++)
#pragma unroll
            for (int j = 0; j < 8; j++)
                acc1[t][j][0] = acc1[t][j][1] = acc1[t][j][2] = acc1[t][j][3] = 0;
        KK_LOOP(1, acc1)

        if (!last) {
            __syncthreads();    // all warps done reading A, B, noise[r&1]
            issue_b(Bcur, r + 1, tid);              // overlaps everything below
            asm volatile("cp.async.commit_group;" ::: "memory");
        }

        EPILOGUE(1, acc1)       // regs + noise buf (r&1) only — no smem hazard

        if (!last) {
            // A-store: pair lanes (l, l^1) -> one u32 word each, half the STS
#pragma unroll
            for (int idx = 0; idx < 32; idx++) {
                int ch = idx >> 4, t = (idx >> 3) & 1, j = idx & 7;
                uint32_t x = pk[idx];
                uint32_t y = __shfl_xor_sync(0xFFFFFFFFu, x, 1);
                uint32_t wA = __byte_perm(x, y, 0x5410);   // row r0loc word
                uint32_t wB = __byte_perm(y, x, 0x7632);   // row r1loc word
                int row = erow0 + t * 16 + ((l & 1) << 3);
                int colq = colqbase + (ch << 6) + (j << 3);
                *(uint32_t*)(smem + OF_A + swz((uint32_t)row, (uint32_t)colq)) =
                    (l & 1) ? wB : wA;
            }
            // stage next round's noise into the other buffer
            ((int*)(smem + OF_NOISE + ((~r & 1) << 10)))[tid] =
                (int)noise[((r + 1) << 8) + tid];
        }
    }
#undef KK_LOOP
#undef EPILOGUE
}

// ---------------- launch ----------------
extern "C" void kernel_launch(void* const* d_in, const int* in_sizes, int n_in,
                              void* d_out, int out_size) {
    const float* state = (const float*)d_in[0];
    const float* mats  = (const float*)d_in[1];
    const float* noise = (const float*)d_in[2];
    float* out = (float*)d_out;

    cvt_mats_kernel<<<ROUNDS * MAT_BYTES / 4 / 256, 256>>>(mats);

    cudaFuncSetAttribute(tenshash_kernel,
                         cudaFuncAttributeMaxDynamicSharedMemorySize, SMEM_TOTAL);
    tenshash_kernel<<<NTILES, 256, SMEM_TOTAL>>>(state, noise, out);
}

// round 7
// speedup vs baseline: 1.0745x; 1.0273x over previous
#include <cuda_runtime.h>
#include <cstdint>

#define ROUNDS 64
#define HID 256
#define BATCH 65536
#define TILE_M 128
#define NTILES (BATCH / TILE_M)      // 512
#define MAT_BYTES (HID * HID)        // 65536 s8 per round matrix

// Pre-converted, pre-swizzled s8 matrices (SMEM image layout), 4 MB. Lives in L2.
__device__ __align__(128) unsigned char g_mat[ROUNDS * MAT_BYTES];

// ---------------- SMEM layout (fits 2 CTAs/SM) ----------------
#define OF_NOISE 0                   // 1 KB
#define OF_MBAR  1024
#define OF_A     2048
#define OF_B     (2048 + 32768)
#define SMEM_TOTAL (OF_B + 65536)    // 100352 bytes

// ---------------- helpers ----------------
__device__ __forceinline__ uint32_t smem_u32(const void* p) {
    uint32_t a;
    asm("{ .reg .u64 t; cvta.to.shared.u64 t, %1; cvt.u32.u64 %0, t; }" : "=r"(a) : "l"(p));
    return a;
}

// byte address inside a [rows x 256B] tile with 16B-chunk XOR swizzle
__device__ __forceinline__ uint32_t swz(uint32_t row, uint32_t col) {
    return row * 256u + ((((col >> 4) ^ (row & 7u)) << 4) | (col & 15u));
}

__device__ __forceinline__ void ldm_x4(uint32_t addr, uint32_t& r0, uint32_t& r1,
                                       uint32_t& r2, uint32_t& r3) {
    asm volatile("ldmatrix.sync.aligned.m8n8.x4.shared.b16 {%0,%1,%2,%3}, [%4];"
                 : "=r"(r0), "=r"(r1), "=r"(r2), "=r"(r3) : "r"(addr));
}

__device__ __forceinline__ void mma_s8(int* c, uint32_t a0, uint32_t a1, uint32_t a2,
                                       uint32_t a3, uint32_t b0, uint32_t b1) {
    asm volatile(
        "mma.sync.aligned.m16n8k32.row.col.s32.s8.s8.s32 "
        "{%0,%1,%2,%3}, {%4,%5,%6,%7}, {%8,%9}, {%0,%1,%2,%3};"
        : "+r"(c[0]), "+r"(c[1]), "+r"(c[2]), "+r"(c[3])
        : "r"(a0), "r"(a1), "r"(a2), "r"(a3), "r"(b0), "r"(b1));
}

#define MBAR_INIT(a, c) \
    asm volatile("mbarrier.init.shared.b64 [%0], %1;" :: "r"(a), "r"(c) : "memory")
#define MBAR_EXPECT(a, b) \
    asm volatile("mbarrier.arrive.expect_tx.shared.b64 _, [%0], %1;" :: "r"(a), "r"(b) : "memory")
#define MBAR_WAIT(a, ph) do { \
    uint32_t _m = (a), _p = (ph), _d; \
    asm volatile("{ .reg .pred p; mbarrier.try_wait.parity.shared.b64 p, [%1], %2; selp.b32 %0,1,0,p; }" \
        : "=r"(_d) : "r"(_m), "r"(_p) : "memory"); \
    if (!_d) { \
        asm volatile("{ .reg .pred P1; WL%=: mbarrier.try_wait.parity.shared.b64 P1, [%0], %1; @P1 bra.uni WD%=; bra.uni WL%=; WD%=: }" \
            :: "r"(_m), "r"(_p) : "memory"); \
    } } while (0)

// one bulk copy: g_mat round r -> smem B buffer, completes on mbar
__device__ __forceinline__ void bulk_b(uint32_t dst, int r, uint32_t mbar) {
    const unsigned char* src = g_mat + (size_t)r * MAT_BYTES;
    asm volatile(
        "cp.async.bulk.shared::cta.global.mbarrier::complete_tx::bytes [%0], [%1], %2, [%3];"
        :: "r"(dst), "l"(src), "r"((uint32_t)MAT_BYTES), "r"(mbar) : "memory");
}

// ---------------- Kernel 1: f32 matrices -> s8 pre-swizzled image ----------------
__global__ void cvt_mats_kernel(const float* __restrict__ m) {
    uint32_t i = blockIdx.x * 256u + threadIdx.x;       // group of 4 elements
    const float4 v = *(const float4*)(m + (size_t)i * 4);
    uint32_t e0 = v.x > 0.5f ? 0x01u : (v.x < -0.5f ? 0xFFu : 0x00u);
    uint32_t e1 = v.y > 0.5f ? 0x01u : (v.y < -0.5f ? 0xFFu : 0x00u);
    uint32_t e2 = v.z > 0.5f ? 0x01u : (v.z < -0.5f ? 0xFFu : 0x00u);
    uint32_t e3 = v.w > 0.5f ? 0x01u : (v.w < -0.5f ? 0xFFu : 0x00u);
    uint32_t pk = e0 | (e1 << 8) | (e2 << 16) | (e3 << 24);
    uint32_t idx = i << 2;
    uint32_t r = idx >> 16, n = (idx >> 8) & 255u, k = idx & 255u;
    *(uint32_t*)(g_mat + (r << 16) + swz(n, k)) = pk;   // k%16 is 4-aligned here
}

// ---------------- Kernel 2: 64 sequential rounds per 128-row tile ----------------
// Warp tiling: warp w -> m-group mg = w&3 (rows mg*32..+32), n-half nh = w>>2
// (cols nh*128..+128). Single A and B smem buffers; next-A staged in registers.
// B filled by cp.async.bulk (elected thread), completion via mbarrier parity.
__global__ __launch_bounds__(256, 2)
void tenshash_kernel(const float* __restrict__ state,
                     const float* __restrict__ noise,
                     float* __restrict__ out) {
    extern __shared__ unsigned char smem[];
    uint32_t sb = smem_u32(smem);
    int tid = threadIdx.x, w = tid >> 5, l = tid & 31;
    int* nsm = (int*)(smem + OF_NOISE);
    const int gbase = blockIdx.x * TILE_M;
    const int mg = w & 3, nh = w >> 2;
    const uint32_t mbar = sb + OF_MBAR;

    // stage noise[0]
    nsm[tid] = (int)noise[tid];

    // init A from state (float {0,1} -> s8), swizzled, u16-packed
    for (int i = tid; i < TILE_M * HID / 2; i += 256) {
        int row = i >> 7;
        int k = (i & 127) << 1;
        const float2 v = *(const float2*)(state + (size_t)(gbase + row) * HID + k);
        uint32_t b0 = v.x > 0.5f ? 1u : 0u;
        uint32_t b1 = v.y > 0.5f ? 1u : 0u;
        *(unsigned short*)(smem + OF_A + swz((uint32_t)row, (uint32_t)k)) =
            (unsigned short)(b0 | (b1 << 8));
    }

    // prologue: init mbarrier and kick off round-0 B bulk copy
    if (tid == 0) {
        MBAR_INIT(mbar, 1);
        MBAR_EXPECT(mbar, MAT_BYTES);
        bulk_b(sb + OF_B, 0, mbar);
    }
    __syncthreads();    // mbar init + A init visible to all

    // lane-invariant addressing pieces
    const uint32_t rowA0 = (uint32_t)(mg * 32) + (l & 15);        // A tile t=0
    const uint32_t rowA1 = rowA0 + 16;                            // A tile t=1
    const uint32_t sA0 = rowA0 & 7u, sA1 = rowA1 & 7u;
    const uint32_t aHalf = (uint32_t)(l >> 4);                    // k-chunk half
    const uint32_t bHalf = ((uint32_t)l >> 3) & 1u;
    const int erow0 = mg * 32 + (l >> 2);                         // epilogue rows
    const int ecol = nh * 128 + ((l & 3) << 1);
    const uint32_t Acur = sb + OF_A;
    const uint32_t Bcur = sb + OF_B;

#pragma unroll 1
    for (int r = 0; r < ROUNDS; r++) {
        MBAR_WAIT(mbar, r & 1);   // B[r] landed
        __syncthreads();          // A stores + noise from r-1 visible
        const bool last = (r == ROUNDS - 1);
        uint32_t pk32[32];  // staged next-A: [ch*16 + t*8 + j]

#pragma unroll 1
        for (int ch = 0; ch < 2; ch++) {           // two 64-col n-chunks
            int acc[2][8][4];
#pragma unroll
            for (int t = 0; t < 2; t++)
#pragma unroll
                for (int j = 0; j < 8; j++)
                    acc[t][j][0] = acc[t][j][1] = acc[t][j][2] = acc[t][j][3] = 0;

#pragma unroll
            for (int kk = 0; kk < 8; kk++) {       // K = 8 x k32
                uint32_t a0[4], a1[4];
                ldm_x4(Acur + rowA0 * 256u + ((((uint32_t)(2 * kk) + aHalf) ^ sA0) << 4),
                       a0[0], a0[1], a0[2], a0[3]);
                ldm_x4(Acur + rowA1 * 256u + ((((uint32_t)(2 * kk) + aHalf) ^ sA1) << 4),
                       a1[0], a1[1], a1[2], a1[3]);
#pragma unroll
                for (int p = 0; p < 4; p++) {      // 16 cols (2 n-tiles) per x4
                    uint32_t bb[4];
                    uint32_t n = (uint32_t)(nh * 128 + ch * 64 + p * 16) +
                                 (((uint32_t)l >> 4) << 3) + (l & 7);
                    uint32_t cb = (uint32_t)(2 * kk) + bHalf;
                    ldm_x4(Bcur + n * 256u + ((cb ^ (n & 7u)) << 4),
                           bb[0], bb[1], bb[2], bb[3]);
                    mma_s8(acc[0][2 * p + 0], a0[0], a0[1], a0[2], a0[3], bb[0], bb[1]);
                    mma_s8(acc[0][2 * p + 1], a0[0], a0[1], a0[2], a0[3], bb[2], bb[3]);
                    mma_s8(acc[1][2 * p + 0], a1[0], a1[1], a1[2], a1[3], bb[0], bb[1]);
                    mma_s8(acc[1][2 * p + 1], a1[0], a1[1], a1[2], a1[3], bb[2], bb[3]);
                }
            }

            // epilogue: v = (acc + noise) % 2 (C trunc == fmod)
#pragma unroll
            for (int t = 0; t < 2; t++) {
#pragma unroll
                for (int j = 0; j < 8; j++) {
                    int col0 = ecol + (ch << 6) + (j << 3);
                    int n0 = nsm[col0], n1 = nsm[col0 + 1];
                    int v00 = (acc[t][j][0] + n0) % 2, v01 = (acc[t][j][1] + n1) % 2;
                    int v10 = (acc[t][j][2] + n0) % 2, v11 = (acc[t][j][3] + n1) % 2;
                    if (!last) {
                        pk32[ch * 16 + t * 8 + j] =
                            (v00 & 255) | ((v01 & 255) << 8) |
                            ((v10 & 255) << 16) | ((uint32_t)(v11 & 255) << 24);
                    } else {
                        float2 o0 = make_float2((float)v00, (float)v01);
                        float2 o1 = make_float2((float)v10, (float)v11);
                        int r0loc = erow0 + t * 16, r1loc = r0loc + 8;
                        *(float2*)(out + (size_t)(gbase + r0loc) * HID + col0) = o0;
                        *(float2*)(out + (size_t)(gbase + r1loc) * HID + col0) = o1;
                    }
                }
            }
        }

        __syncthreads();    // all reads of A, B, noise for round r done
        if (!last) {
            // issue next B bulk copy (same single buffer)
            if (tid == 0) {
                MBAR_EXPECT(mbar, MAT_BYTES);
                bulk_b(Bcur, r + 1, mbar);
            }
            // store staged next-A to SMEM
#pragma unroll
            for (int ch = 0; ch < 2; ch++)
#pragma unroll
                for (int t = 0; t < 2; t++)
#pragma unroll
                    for (int j = 0; j < 8; j++) {
                        uint32_t v = pk32[ch * 16 + t * 8 + j];
                        int col0 = ecol + (ch << 6) + (j << 3);
                        int r0loc = erow0 + t * 16, r1loc = r0loc + 8;
                        *(unsigned short*)(smem + OF_A + swz((uint32_t)r0loc, (uint32_t)col0)) =
                            (unsigned short)(v & 0xFFFFu);
                        *(unsigned short*)(smem + OF_A + swz((uint32_t)r1loc, (uint32_t)col0)) =
                            (unsigned short)(v >> 16);
                    }
            // stage next round's noise
            nsm[tid] = (int)noise[((r + 1) << 8) + tid];
        }
    }
}

// ---------------- launch ----------------
extern "C" void kernel_launch(void* const* d_in, const int* in_sizes, int n_in,
                              void* d_out, int out_size) {
    const float* state = (const float*)d_in[0];
    const float* mats  = (const float*)d_in[1];
    const float* noise = (const float*)d_in[2];
    float* out = (float*)d_out;

    cvt_mats_kernel<<<ROUNDS * MAT_BYTES / 4 / 256, 256>>>(mats);

    cudaFuncSetAttribute(tenshash_kernel,
                         cudaFuncAttributeMaxDynamicSharedMemorySize, SMEM_TOTAL);
    tenshash_kernel<<<NTILES, 256, SMEM_TOTAL>>>(state, noise, out);
}

// round 8
// speedup vs baseline: 1.0936x; 1.0178x over previous
#include <cuda_runtime.h>
#include <cstdint>

#define ROUNDS 64
#define HID 256
#define BATCH 65536
#define TILE_M 128
#define NTILES (BATCH / TILE_M)      // 512
#define MAT_BYTES (HID * HID)        // 65536 s8 per round matrix

// Pre-converted, pre-swizzled s8 matrices (SMEM image layout), 4 MB. Lives in L2.
__device__ __align__(128) unsigned char g_mat[ROUNDS * MAT_BYTES];

// ---------------- SMEM layout (fits 2 CTAs/SM) ----------------
#define OF_NOISE 0
#define OF_A     1024
#define OF_B     (1024 + 32768)
#define SMEM_TOTAL (OF_B + 65536)    // 99328 bytes

// ---------------- helpers ----------------
__device__ __forceinline__ uint32_t smem_u32(const void* p) {
    uint32_t a;
    asm("{ .reg .u64 t; cvta.to.shared.u64 t, %1; cvt.u32.u64 %0, t; }" : "=r"(a) : "l"(p));
    return a;
}

// byte address inside a [rows x 256B] tile with 16B-chunk XOR swizzle
__device__ __forceinline__ uint32_t swz(uint32_t row, uint32_t col) {
    return row * 256u + ((((col >> 4) ^ (row & 7u)) << 4) | (col & 15u));
}

__device__ __forceinline__ void ldm_x4(uint32_t addr, uint32_t& r0, uint32_t& r1,
                                       uint32_t& r2, uint32_t& r3) {
    asm volatile("ldmatrix.sync.aligned.m8n8.x4.shared.b16 {%0,%1,%2,%3}, [%4];"
                 : "=r"(r0), "=r"(r1), "=r"(r2), "=r"(r3) : "r"(addr));
}

__device__ __forceinline__ void mma_s8(int* c, uint32_t a0, uint32_t a1, uint32_t a2,
                                       uint32_t a3, uint32_t b0, uint32_t b1) {
    asm volatile(
        "mma.sync.aligned.m16n8k32.row.col.s32.s8.s8.s32 "
        "{%0,%1,%2,%3}, {%4,%5,%6,%7}, {%8,%9}, {%0,%1,%2,%3};"
        : "+r"(c[0]), "+r"(c[1]), "+r"(c[2]), "+r"(c[3])
        : "r"(a0), "r"(a1), "r"(a2), "r"(a3), "r"(b0), "r"(b1));
}

__device__ __forceinline__ void issue_b(uint32_t dst, int r, int tid) {
    const unsigned char* src = g_mat + (size_t)r * MAT_BYTES;
#pragma unroll
    for (int j = 0; j < 16; j++) {
        uint32_t off = (uint32_t)(tid + (j << 8)) << 4;
        asm volatile("cp.async.cg.shared.global [%0], [%1], 16;"
                     :: "r"(dst + off), "l"(src + off) : "memory");
    }
}

// ---------------- Kernel 1: f32 matrices -> s8 pre-swizzled image ----------------
__global__ void cvt_mats_kernel(const float* __restrict__ m) {
    uint32_t i = blockIdx.x * 256u + threadIdx.x;       // group of 4 elements
    const float4 v = *(const float4*)(m + (size_t)i * 4);
    uint32_t e0 = v.x > 0.5f ? 0x01u : (v.x < -0.5f ? 0xFFu : 0x00u);
    uint32_t e1 = v.y > 0.5f ? 0x01u : (v.y < -0.5f ? 0xFFu : 0x00u);
    uint32_t e2 = v.z > 0.5f ? 0x01u : (v.z < -0.5f ? 0xFFu : 0x00u);
    uint32_t e3 = v.w > 0.5f ? 0x01u : (v.w < -0.5f ? 0xFFu : 0x00u);
    uint32_t pk = e0 | (e1 << 8) | (e2 << 16) | (e3 << 24);
    uint32_t idx = i << 2;
    uint32_t r = idx >> 16, n = (idx >> 8) & 255u, k = idx & 255u;
    *(uint32_t*)(g_mat + (r << 16) + swz(n, k)) = pk;   // k%16 is 4-aligned here
}

// ---------------- Kernel 2: 64 sequential rounds per 128-row tile ----------------
// Warp tiling: warp w -> m-group mg = w&3 (rows mg*32..+32), n-half nh = w>>2
// (cols nh*128..+128). Single A and B smem buffers; next-A staged in registers.
// Next-round noise prefetched into a register at round top (LDG hidden under
// the kk loops), stored to SMEM after the bottom barrier.
__global__ __launch_bounds__(256, 2)
void tenshash_kernel(const float* __restrict__ state,
                     const float* __restrict__ noise,
                     float* __restrict__ out) {
    extern __shared__ unsigned char smem[];
    uint32_t sb = smem_u32(smem);
    int tid = threadIdx.x, w = tid >> 5, l = tid & 31;
    int* nsm = (int*)(smem + OF_NOISE);
    const int gbase = blockIdx.x * TILE_M;
    const int mg = w & 3, nh = w >> 2;

    // stage noise[0]
    nsm[tid] = (int)noise[tid];

    // init A from state (float {0,1} -> s8), swizzled, u16-packed
    for (int i = tid; i < TILE_M * HID / 2; i += 256) {
        int row = i >> 7;
        int k = (i & 127) << 1;
        const float2 v = *(const float2*)(state + (size_t)(gbase + row) * HID + k);
        uint32_t b0 = v.x > 0.5f ? 1u : 0u;
        uint32_t b1 = v.y > 0.5f ? 1u : 0u;
        *(unsigned short*)(smem + OF_A + swz((uint32_t)row, (uint32_t)k)) =
            (unsigned short)(b0 | (b1 << 8));
    }

    // prologue: prefetch B for round 0
    issue_b(sb + OF_B, 0, tid);
    asm volatile("cp.async.commit_group;" ::: "memory");

    // lane-invariant addressing pieces
    const uint32_t rowA0 = (uint32_t)(mg * 32) + (l & 15);        // A tile t=0
    const uint32_t rowA1 = rowA0 + 16;                            // A tile t=1
    const uint32_t sA0 = rowA0 & 7u, sA1 = rowA1 & 7u;
    const uint32_t aHalf = (uint32_t)(l >> 4);                    // k-chunk half
    const uint32_t bHalf = ((uint32_t)l >> 3) & 1u;
    const int erow0 = mg * 32 + (l >> 2);                         // epilogue rows
    const int ecol = nh * 128 + ((l & 3) << 1);
    const uint32_t Acur = sb + OF_A;
    const uint32_t Bcur = sb + OF_B;

#pragma unroll 1
    for (int r = 0; r < ROUNDS; r++) {
        const bool last = (r == ROUNDS - 1);
        // prefetch next round's noise早 (register; no smem touched -> legal here)
        int nz = 0;
        if (!last) nz = (int)noise[((r + 1) << 8) + tid];

        asm volatile("cp.async.wait_group 0;" ::: "memory");
        __syncthreads();    // B[r] ready; A stores + noise from r-1 visible
        uint32_t pk32[32];  // staged next-A: [ch*16 + t*8 + j]

#pragma unroll 1
        for (int ch = 0; ch < 2; ch++) {           // two 64-col n-chunks
            int acc[2][8][4];
#pragma unroll
            for (int t = 0; t < 2; t++)
#pragma unroll
                for (int j = 0; j < 8; j++)
                    acc[t][j][0] = acc[t][j][1] = acc[t][j][2] = acc[t][j][3] = 0;

#pragma unroll
            for (int kk = 0; kk < 8; kk++) {       // K = 8 x k32
                uint32_t a0[4], a1[4];
                ldm_x4(Acur + rowA0 * 256u + ((((uint32_t)(2 * kk) + aHalf) ^ sA0) << 4),
                       a0[0], a0[1], a0[2], a0[3]);
                ldm_x4(Acur + rowA1 * 256u + ((((uint32_t)(2 * kk) + aHalf) ^ sA1) << 4),
                       a1[0], a1[1], a1[2], a1[3]);
#pragma unroll
                for (int p = 0; p < 4; p++) {      // 16 cols (2 n-tiles) per x4
                    uint32_t bb[4];
                    uint32_t n = (uint32_t)(nh * 128 + ch * 64 + p * 16) +
                                 (((uint32_t)l >> 4) << 3) + (l & 7);
                    uint32_t cb = (uint32_t)(2 * kk) + bHalf;
                    ldm_x4(Bcur + n * 256u + ((cb ^ (n & 7u)) << 4),
                           bb[0], bb[1], bb[2], bb[3]);
                    mma_s8(acc[0][2 * p + 0], a0[0], a0[1], a0[2], a0[3], bb[0], bb[1]);
                    mma_s8(acc[0][2 * p + 1], a0[0], a0[1], a0[2], a0[3], bb[2], bb[3]);
                    mma_s8(acc[1][2 * p + 0], a1[0], a1[1], a1[2], a1[3], bb[0], bb[1]);
                    mma_s8(acc[1][2 * p + 1], a1[0], a1[1], a1[2], a1[3], bb[2], bb[3]);
                }
            }

            // epilogue: v = (acc + noise) % 2 (C trunc == fmod); noise hoisted over t
#pragma unroll
            for (int j = 0; j < 8; j++) {
                int col0 = ecol + (ch << 6) + (j << 3);
                int n0 = nsm[col0], n1 = nsm[col0 + 1];
#pragma unroll
                for (int t = 0; t < 2; t++) {
                    int v00 = (acc[t][j][0] + n0) % 2, v01 = (acc[t][j][1] + n1) % 2;
                    int v10 = (acc[t][j][2] + n0) % 2, v11 = (acc[t][j][3] + n1) % 2;
                    if (!last) {
                        pk32[ch * 16 + t * 8 + j] =
                            (v00 & 255) | ((v01 & 255) << 8) |
                            ((v10 & 255) << 16) | ((uint32_t)(v11 & 255) << 24);
                    } else {
                        float2 o0 = make_float2((float)v00, (float)v01);
                        float2 o1 = make_float2((float)v10, (float)v11);
                        int r0loc = erow0 + t * 16, r1loc = r0loc + 8;
                        *(float2*)(out + (size_t)(gbase + r0loc) * HID + col0) = o0;
                        *(float2*)(out + (size_t)(gbase + r1loc) * HID + col0) = o1;
                    }
                }
            }
        }

        __syncthreads();    // all reads of A, B, noise for round r done
        if (!last) {
            // issue next B load (into same single buffer)
            issue_b(Bcur, r + 1, tid);
            asm volatile("cp.async.commit_group;" ::: "memory");
            // store staged next-A to SMEM
#pragma unroll
            for (int ch = 0; ch < 2; ch++)
#pragma unroll
                for (int t = 0; t < 2; t++)
#pragma unroll
                    for (int j = 0; j < 8; j++) {
                        uint32_t v = pk32[ch * 16 + t * 8 + j];
                        int col0 = ecol + (ch << 6) + (j << 3);
                        int r0loc = erow0 + t * 16, r1loc = r0loc + 8;
                        *(unsigned short*)(smem + OF_A + swz((uint32_t)r0loc, (uint32_t)col0)) =
                            (unsigned short)(v & 0xFFFFu);
                        *(unsigned short*)(smem + OF_A + swz((uint32_t)r1loc, (uint32_t)col0)) =
                            (unsigned short)(v >> 16);
                    }
            // next round's noise: already in register, just store
            nsm[tid] = nz;
        }
    }
}

// ---------------- launch ----------------
extern "C" void kernel_launch(void* const* d_in, const int* in_sizes, int n_in,
                              void* d_out, int out_size) {
    const float* state = (const float*)d_in[0];
    const float* mats  = (const float*)d_in[1];
    const float* noise = (const float*)d_in[2];
    float* out = (float*)d_out;

    cvt_mats_kernel<<<ROUNDS * MAT_BYTES / 4 / 256, 256>>>(mats);

    cudaFuncSetAttribute(tenshash_kernel,
                         cudaFuncAttributeMaxDynamicSharedMemorySize, SMEM_TOTAL);
    tenshash_kernel<<<NTILES, 256, SMEM_TOTAL>>>(state, noise, out);
}